// round 9
// baseline (speedup 1.0000x reference)
#include <cuda_runtime.h>
#include <math.h>

#define T    128
#define D    64
#define H    256
#define HK   128
#define DD   (D*D)
#define ITERS 3
#define NB   128
#define NT   1024
#define NSLOT 256
#define NBAR 16
#define NLEAF 16

// ---- scratch (static device globals; no runtime allocation) ----
__device__ float AT_g[T*HK*T];         // 8 MB  AT[(j*HK+h)][i] = w_ij * tanh(...)
__device__ float W2T_g[HK*DD];         // 2 MB  Wk2 transposed per-row: [h][e][d]
__device__ float bk2T_g[DD];           //       bk2 transposed: [e][d]
__device__ float fyT_g[D*T];           //       f(y) transposed: [e][j]
__device__ float c_g[T*D];
__device__ float M3_g[T*HK*D];         // 4 MB
__device__ float Gpart_g[NSLOT*T*D];   // 8 MB  slot = bid*2+hg (j=bid / j=127-bid, h-half hg)
__device__ float G_g[T*D];

// hierarchical grid barrier (replay-safe: last root-departer resets all)
__device__ unsigned lfA[NBAR][NLEAF];
__device__ unsigned rtA[NBAR];
__device__ unsigned lfD[NBAR][NLEAF];
__device__ unsigned rtD[NBAR];

__device__ __forceinline__ void gsync(int b) {
    __syncthreads();
    if (threadIdx.x == 0) {
        __threadfence();
        int leaf = blockIdx.x & (NLEAF - 1);
        if (atomicAdd(&lfA[b][leaf], 1u) == 7u)
            atomicAdd(&rtA[b], 1u);
        while (*(volatile unsigned*)&rtA[b] < (unsigned)NLEAF) { }
        __threadfence();
        if (atomicAdd(&lfD[b][leaf], 1u) == 7u) {
            if (atomicAdd(&rtD[b], 1u) == (unsigned)(NLEAF - 1)) {
                #pragma unroll
                for (int l = 0; l < NLEAF; l++) { lfA[b][l] = 0u; lfD[b][l] = 0u; }
                rtA[b] = 0u;
                __threadfence();
                rtD[b] = 0u;
            }
        }
    }
    __syncthreads();
}

__device__ __forceinline__ void hsync(int hg) {   // named barrier over one 512-thread half
    asm volatile("bar.sync %0, %1;" :: "r"(1 + hg), "r"(512) : "memory");
}

// trapezoid weight w[i][j]: w = dt*(j<=i); w[i,i]*=0.5; w[:,0]*=0.5; w[0,:]=0
__device__ __forceinline__ float wfun(int i, int j, float dt) {
    if (i == 0 || j > i) return 0.0f;
    float v = dt;
    if (j == i) v *= 0.5f;
    if (j == 0) v *= 0.5f;
    return v;
}

__global__ void __launch_bounds__(NT, 1) mega(
    const float* __restrict__ z0, const float* __restrict__ t,
    const float* __restrict__ W1, const float* __restrict__ b1,
    const float* __restrict__ W2, const float* __restrict__ b2,
    const float* __restrict__ Wk1, const float* __restrict__ bk1,
    const float* __restrict__ Wk2, const float* __restrict__ bk2,
    float* __restrict__ out)
{
    extern __shared__ float sbuf[];              // 48 KB dynamic, multipurpose
    __shared__ float wa[HK], wb[HK], bkk[HK], ts[T];
    __shared__ float yrow[D], hid[H], fyr[D];
    __shared__ float part16[16][D];
    __shared__ float hidpart[4][H];

    int bid = blockIdx.x, tid = threadIdx.x;

    // ================= SETUP =================
    // W2T[h=bid][e][d] = Wk2[h][d*64+e]
    #pragma unroll
    for (int r = 0; r < 4; r++) {
        int idx = tid + r * 1024;
        sbuf[(idx >> 6) * 67 + (idx & 63)] = Wk2[bid * DD + idx];
    }
    __syncthreads();
    #pragma unroll
    for (int r = 0; r < 4; r++) {
        int idx = tid + r * 1024;
        W2T_g[bid * DD + idx] = sbuf[(idx & 63) * 67 + (idx >> 6)];
    }
    __syncthreads();
    if (bid == 0) {            // bk2T (block-uniform branch)
        #pragma unroll
        for (int r = 0; r < 4; r++) {
            int idx = tid + r * 1024;
            sbuf[(idx >> 6) * 67 + (idx & 63)] = bk2[idx];
        }
        __syncthreads();
        #pragma unroll
        for (int r = 0; r < 4; r++) {
            int idx = tid + r * 1024;
            bk2T_g[idx] = sbuf[(idx & 63) * 67 + (idx >> 6)];
        }
    }
    if (tid < HK) { wa[tid] = Wk1[tid]; wb[tid] = Wk1[HK + tid]; bkk[tid] = bk1[tid]; }
    if (tid < T)  ts[tid] = t[tid];
    __syncthreads();
    float dt = ts[1] - ts[0];
    // AT[(j=bid)*HK + h][i]  -- coalesced over i
    {
        int j = bid;
        float tj = ts[j];
        #pragma unroll 4
        for (int r = 0; r < 16; r++) {
            int idx = tid + r * 1024;              // 0..16383
            int h = idx >> 7, i = idx & 127;
            float v = tanhf(ts[i] * wa[h] + tj * wb[h] + bkk[h]);
            AT_g[j * (HK * T) + idx] = wfun(i, j, dt) * v;
        }
    }

    int bar = 0;
    gsync(bar++);

    // ================= FIXED-POINT ITERATIONS =================
    for (int it = 0; it < ITERS; it++) {
        // ---- phase F (block j): y_j = y0 + (w@G)_j (fused), then fy[j], c[j] ----
        {
            int j = bid;
            int d = tid & 63, p = tid >> 6;        // 16-way split
            if (it == 0) {
                if (tid < D) yrow[tid] = z0[tid];
            } else {
                float s = 0.0f;
                for (int i = p; i <= j; i += 16)
                    s += wfun(j, i, dt) * __ldcg(&G_g[i * D + d]);
                part16[p][d] = s;
                __syncthreads();
                if (p == 0) {
                    float acc = z0[d];
                    #pragma unroll
                    for (int r = 0; r < 16; r++) acc += part16[r][d];
                    yrow[d] = acc;
                }
            }
            __syncthreads();
            // hidden: h = tid&255, 4-way split over e
            {
                int h = tid & 255, q = tid >> 8;
                float s = (q == 0) ? b1[h] : 0.0f;
                #pragma unroll
                for (int ee = 0; ee < 16; ee++) {
                    int e = q * 16 + ee;
                    s += yrow[e] * W1[e * H + h];
                }
                hidpart[q][h] = s;
            }
            __syncthreads();
            if (tid < H)
                hid[tid] = tanhf(hidpart[0][tid] + hidpart[1][tid] + hidpart[2][tid] + hidpart[3][tid]);
            __syncthreads();
            // fy: 16-way split over h (16 each)
            {
                float s = 0.0f;
                #pragma unroll
                for (int hh = 0; hh < 16; hh++) {
                    int h = p * 16 + hh;
                    s += hid[h] * W2[h * D + d];
                }
                part16[p][d] = s;
            }
            __syncthreads();
            if (p == 0) {
                float f = b2[d];
                #pragma unroll
                for (int r = 0; r < 16; r++) f += part16[r][d];
                fyr[d] = f;
                fyT_g[d * T + j] = f;              // transposed [e][j]
            }
            __syncthreads();
            // c: 16-way split over e (4 each)
            {
                float s = 0.0f;
                #pragma unroll
                for (int ee = 0; ee < 4; ee++) {
                    int e = p * 4 + ee;
                    s += bk2T_g[e * D + d] * fyr[e];
                }
                part16[p][d] = s;
            }
            __syncthreads();
            if (p == 0) {
                float cc = 0.0f;
                #pragma unroll
                for (int r = 0; r < 16; r++) cc += part16[r][d];
                c_g[j * D + d] = cc;
            }
        }
        gsync(bar++);

        // ---- phase M3 (block h): halves split j-range; shared w2s stage ----
        {
            int h = bid;
            int hg = tid >> 9, tg = tid & 511;
            float* w2s  = sbuf;                    // [e][d] 4096 (shared)
            float* fyTs = sbuf + 4096 + hg * 4096; // [e][j_local 64] per half
            #pragma unroll
            for (int r = 0; r < 4; r++)
                w2s[tid + r * 1024] = W2T_g[h * DD + tid + r * 1024];
            // fyTs: 64e x 64j half, 1024 float4 / 512 threads
            #pragma unroll
            for (int r = 0; r < 2; r++) {
                int lin = tg + r * 512;            // 0..1023 float4 index
                int e = lin >> 4, c4 = lin & 15;
                ((float4*)fyTs)[lin] =
                    __ldcg(((const float4*)(fyT_g + e * T + hg * 64)) + c4);
            }
            __syncthreads();
            int tx = tg & 15, ty = tg >> 4;        // 4 d, 2 j per thread
            float acc[2][4] = {};
            #pragma unroll
            for (int e = 0; e < D; e++) {
                float4 wv = ((const float4*)w2s)[e * 16 + tx];
                float2 fv = *(const float2*)&fyTs[e * 64 + ty * 2];
                acc[0][0] += fv.x * wv.x; acc[0][1] += fv.x * wv.y;
                acc[0][2] += fv.x * wv.z; acc[0][3] += fv.x * wv.w;
                acc[1][0] += fv.y * wv.x; acc[1][1] += fv.y * wv.y;
                acc[1][2] += fv.y * wv.z; acc[1][3] += fv.y * wv.w;
            }
            #pragma unroll
            for (int jl = 0; jl < 2; jl++) {
                int j = hg * 64 + ty * 2 + jl;
                float4 o = make_float4(acc[jl][0], acc[jl][1], acc[jl][2], acc[jl][3]);
                __stcg((float4*)&M3_g[(j * HK + h) * D + tx * 4], o);
            }
        }
        gsync(bar++);

        // ---- phase G: two concurrent 512-thread halves (named barriers) ----
        // half hg: j = hg ? 127-bid : bid, h-HALF [hg*64, hg*64+64) in 2 chunks of 32.
        // Coverage: (j,h-low) from block j's half0; (j,h-high) from block (127-j)'s half1
        // -> every (j,h) pair exactly once (this was double-counted in round 8).
        {
            int hg = tid >> 9, tg = tid & 511;
            int j = hg ? (127 - bid) : bid;
            int hoff = j * HK + hg * 64;           // this half's 64-wide h slice
            float* As = sbuf + hg * 6144;          // [hh][i] 32x128
            float* Bs = As + 4096;                 // [hh][d] 32x64
            int tx = tg & 15, ty = tg >> 4;        // 4 d cols, 4 i rows
            float acc[4][4] = {};
            bool active = (ty * 4 + 3) >= j;
            #pragma unroll
            for (int cb = 0; cb < 2; cb++) {
                hsync(hg);
                const float4* a4 = (const float4*)&AT_g[(hoff + cb * 32) * T];
                float4* As4 = (float4*)As;
                #pragma unroll
                for (int r = 0; r < 2; r++)
                    As4[tg + r * 512] = a4[tg + r * 512];
                ((float4*)Bs)[tg] = __ldcg(((const float4*)&M3_g[(hoff + cb * 32) * D]) + tg);
                hsync(hg);
                if (active) {
                    #pragma unroll
                    for (int hh = 0; hh < 32; hh++) {
                        float4 a = *(const float4*)&As[hh * 128 + ty * 4];
                        float4 b = *(const float4*)&Bs[hh * 64 + tx * 4];
                        acc[0][0] += a.x * b.x; acc[0][1] += a.x * b.y;
                        acc[0][2] += a.x * b.z; acc[0][3] += a.x * b.w;
                        acc[1][0] += a.y * b.x; acc[1][1] += a.y * b.y;
                        acc[1][2] += a.y * b.z; acc[1][3] += a.y * b.w;
                        acc[2][0] += a.z * b.x; acc[2][1] += a.z * b.y;
                        acc[2][2] += a.z * b.z; acc[2][3] += a.z * b.w;
                        acc[3][0] += a.w * b.x; acc[3][1] += a.w * b.y;
                        acc[3][2] += a.w * b.z; acc[3][3] += a.w * b.w;
                    }
                }
            }
            if (active) {
                float* gp = &Gpart_g[(bid * 2 + hg) * (T * D)];
                #pragma unroll
                for (int r = 0; r < 4; r++) {
                    float4 o = make_float4(acc[r][0], acc[r][1], acc[r][2], acc[r][3]);
                    *(float4*)&gp[(ty * 4 + r) * D + tx * 4] = o;
                }
            }
        }
        gsync(bar++);

        // ---- phase R (block i): reduce 256 slots (skip empties) + bias -> G ----
        {
            int i = bid;
            int d = tid & 63, p = tid >> 6;        // 16-way
            float s = 0.0f;
            for (int sl = p; sl < NSLOT; sl += 16) {
                int js = (sl & 1) ? (127 - (sl >> 1)) : (sl >> 1);
                if (js <= i)
                    s += __ldcg(&Gpart_g[sl * (T * D) + i * D + d]);
            }
            for (int jj = p; jj <= i; jj += 16)
                s += wfun(i, jj, dt) * __ldcg(&c_g[jj * D + d]);
            part16[p][d] = s;
            __syncthreads();
            if (p == 0) {
                float acc = 0.0f;
                #pragma unroll
                for (int r = 0; r < 16; r++) acc += part16[r][d];
                G_g[i * D + d] = acc;
            }
        }
        gsync(bar++);
    }

    // ---- tail: block 127 computes out = y0 + (w@G)_{127} ----
    if (bid == T - 1) {
        int d = tid & 63, p = tid >> 6;
        float s = 0.0f;
        for (int i = p; i < T; i += 16)
            s += wfun(T - 1, i, dt) * __ldcg(&G_g[i * D + d]);
        part16[p][d] = s;
        __syncthreads();
        if (p == 0) {
            float acc = z0[d];
            #pragma unroll
            for (int r = 0; r < 16; r++) acc += part16[r][d];
            out[d] = acc;
        }
    }
}

extern "C" void kernel_launch(void* const* d_in, const int* in_sizes, int n_in,
                              void* d_out, int out_size) {
    const float* z0  = (const float*)d_in[0];
    const float* t   = (const float*)d_in[1];
    const float* W1  = (const float*)d_in[2];
    const float* b1  = (const float*)d_in[3];
    const float* W2  = (const float*)d_in[4];
    const float* b2  = (const float*)d_in[5];
    const float* Wk1 = (const float*)d_in[6];
    const float* bk1 = (const float*)d_in[7];
    const float* Wk2 = (const float*)d_in[8];
    const float* bk2 = (const float*)d_in[9];
    float* out = (float*)d_out;

    static int attr_done = 0;
    if (!attr_done) {
        cudaFuncSetAttribute(mega, cudaFuncAttributeMaxDynamicSharedMemorySize, 64 * 1024);
        attr_done = 1;
    }
    mega<<<NB, NT, 49152>>>(z0, t, W1, b1, W2, b2, Wk1, bk1, Wk2, bk2, out);
}